// round 1
// baseline (speedup 1.0000x reference)
#include <cuda_runtime.h>
#include <math.h>

#define IH 512
#define IW 512
#define IB 8
#define NPIX (IB*IH*IW)   // 2097152
#define HW (IH*IW)

// ---------------- device globals (scratch; no allocation allowed) ----------------
__device__ float d_w[5][33];                         // 1D gaussian weights per sigma
__device__ float d_tmp[(size_t)7*5*IB*HW];           // pass1 output: [pair][field][b][y][x]  (280MB)
__device__ float d_tmpL1[(size_t)3*IB*HW];           // L1 pass1 output (24MB)
__device__ float d_cs[7][NPIX];                      // cs^mult per pair (56MB)
__device__ float d_l3[NPIX];                         // l^3 for pair 6
__device__ float d_gl1[NPIX];                        // gaussian L1
__device__ double d_sum;

// pair tables: pair -> (input channel, sigma idx, multiplicity)
__constant__ int   c_ch[7]   = {0,0,1,1,1,2,2};
__constant__ int   c_sig[7]  = {0,1,1,2,3,3,4};
__constant__ int   c_mult[7] = {3,2,1,3,1,2,3};
__constant__ float c_sigma[5] = {0.5f, 1.0f, 2.0f, 4.0f, 8.0f};

#define C1F 1e-4f
#define C2F 9e-4f

// ---------------- init: weights + zero the reduction accumulator ----------------
__global__ void initK() {
    int t = threadIdx.x;
    if (t == 0) d_sum = 0.0;
    if (t < 5) {
        float s = c_sigma[t];
        float inv2s2 = 1.0f / (2.0f * s * s);
        float v[33];
        float sum = 0.0f;
        for (int i = 0; i < 33; i++) {
            float d = (float)(i - 16);
            v[i] = expf(-d * d * inv2s2);
            sum += v[i];
        }
        float inv = 1.0f / sum;
        for (int i = 0; i < 33; i++) d_w[t][i] = v[i] * inv;
    }
}

// ---------------- pass1: vertical blur of (x, y, x^2, y^2, xy) ----------------
// grid: (128 = 16 xtiles * 8 ytiles, B, npairs), block 256
// tile: 32 cols x 64 output rows; smem tile (64+2R) rows x 32 cols x 5 fields
template<int R>
__global__ void __launch_bounds__(256) pass1_ssim(const float* __restrict__ xin,
                                                  const float* __restrict__ yin,
                                                  int pairBase) {
    constexpr int ROWS = 64 + 2 * R;
    const int pair = pairBase + blockIdx.z;
    const int ch = c_ch[pair], sg = c_sig[pair];
    const int b = blockIdx.y;
    const int xt = blockIdx.x & 15;
    const int yt = blockIdx.x >> 4;
    const int x0 = xt * 32, y0 = yt * 64;

    extern __shared__ float ss[];      // [5][ROWS][32]
    __shared__ float sw[33];
    const int tid = threadIdx.x;
    if (tid < 33) sw[tid] = d_w[sg][tid];

    const float* xp = xin + (size_t)(b * 3 + ch) * HW;
    const float* yp = yin + (size_t)(b * 3 + ch) * HW;

    for (int e = tid; e < ROWS * 32; e += 256) {
        int col = e & 31, row = e >> 5;
        int gy = y0 - R + row;
        float xv = 0.0f, yv = 0.0f;
        if (gy >= 0 && gy < IH) {
            int gi = gy * IW + x0 + col;
            xv = xp[gi]; yv = yp[gi];
        }
        ss[0 * ROWS * 32 + e] = xv;
        ss[1 * ROWS * 32 + e] = yv;
        ss[2 * ROWS * 32 + e] = xv * xv;
        ss[3 * ROWS * 32 + e] = yv * yv;
        ss[4 * ROWS * 32 + e] = xv * yv;
    }
    __syncthreads();

    const int lane = tid & 31, wrp = tid >> 5;
    const int base = wrp * 8;

    float acc[5][8], win[5][8];
    #pragma unroll
    for (int f = 0; f < 5; f++)
        #pragma unroll
        for (int t = 0; t < 8; t++) {
            acc[f][t] = 0.0f;
            win[f][t] = ss[f * ROWS * 32 + (base + t) * 32 + lane];
        }

    for (int kk = 0; kk <= 2 * R; kk++) {
        float wk = sw[16 - R + kk];
        #pragma unroll
        for (int f = 0; f < 5; f++)
            #pragma unroll
            for (int t = 0; t < 8; t++)
                acc[f][t] = fmaf(wk, win[f][t], acc[f][t]);
        if (kk < 2 * R) {
            #pragma unroll
            for (int f = 0; f < 5; f++) {
                #pragma unroll
                for (int t = 0; t < 7; t++) win[f][t] = win[f][t + 1];
                win[f][7] = ss[f * ROWS * 32 + (base + 8 + kk) * 32 + lane];
            }
        }
    }

    #pragma unroll
    for (int f = 0; f < 5; f++) {
        size_t ob = ((size_t)(pair * 5 + f) * IB + b) * HW;
        #pragma unroll
        for (int t = 0; t < 8; t++)
            d_tmp[ob + (size_t)(y0 + base + t) * IW + x0 + lane] = acc[f][t];
    }
}

// ---------------- pass2: horizontal blur + l/cs epilogue ----------------
// grid: (128 = 8 xtiles * 16 ytiles, B, npairs), block 256
// tile: 64 output cols x 32 rows; smem [5][COLS][33] column-major (+1 pad)
template<int R>
__global__ void __launch_bounds__(256) pass2_ssim(int pairBase) {
    constexpr int COLS = 64 + 2 * R;
    const int pair = pairBase + blockIdx.z;
    const int sg = c_sig[pair], mult = c_mult[pair];
    const int b = blockIdx.y;
    const int xt = blockIdx.x & 7;
    const int yt = blockIdx.x >> 3;
    const int x0 = xt * 64, y0 = yt * 32;

    extern __shared__ float ss[];      // [5][COLS][33]
    __shared__ float sw[33];
    const int tid = threadIdx.x;
    if (tid < 33) sw[tid] = d_w[sg][tid];

    #pragma unroll
    for (int f = 0; f < 5; f++) {
        const float* tp = d_tmp + ((size_t)(pair * 5 + f) * IB + b) * HW;
        for (int e = tid; e < COLS * 32; e += 256) {
            int c = e % COLS, r = e / COLS;
            int gx = x0 - R + c;
            float v = 0.0f;
            if (gx >= 0 && gx < IW) v = tp[(size_t)(y0 + r) * IW + gx];
            ss[(f * COLS + c) * 33 + r] = v;
        }
    }
    __syncthreads();

    const int lane = tid & 31, wrp = tid >> 5;
    const int basec = wrp * 8;

    float acc[5][8], win[5][8];
    #pragma unroll
    for (int f = 0; f < 5; f++)
        #pragma unroll
        for (int t = 0; t < 8; t++) {
            acc[f][t] = 0.0f;
            win[f][t] = ss[(f * COLS + basec + t) * 33 + lane];
        }

    for (int kk = 0; kk <= 2 * R; kk++) {
        float wk = sw[16 - R + kk];
        #pragma unroll
        for (int f = 0; f < 5; f++)
            #pragma unroll
            for (int t = 0; t < 8; t++)
                acc[f][t] = fmaf(wk, win[f][t], acc[f][t]);
        if (kk < 2 * R) {
            #pragma unroll
            for (int f = 0; f < 5; f++) {
                #pragma unroll
                for (int t = 0; t < 7; t++) win[f][t] = win[f][t + 1];
                win[f][7] = ss[(f * COLS + basec + 8 + kk) * 33 + lane];
            }
        }
    }

    const int gy = y0 + lane;
    #pragma unroll
    for (int t = 0; t < 8; t++) {
        float mux = acc[0][t], muy = acc[1][t];
        float mxx = acc[2][t], myy = acc[3][t], mxy = acc[4][t];
        float A = mux * muy;
        float sxy = mxy - A;
        float sx2 = mxx - mux * mux;
        float sy2 = myy - muy * muy;
        float cs = (2.0f * sxy + C2F) / (sx2 + sy2 + C2F);
        float csm = (mult == 1) ? cs : ((mult == 2) ? cs * cs : cs * cs * cs);
        size_t oi = ((size_t)b * IH + gy) * IW + x0 + basec + t;
        d_cs[pair][oi] = csm;
        if (pair == 6) {
            float l = (2.0f * A + C1F) / (mux * mux + muy * muy + C1F);
            d_l3[oi] = l * l * l;
        }
    }
}

// ---------------- L1 pass1: vertical blur of |x-y| per channel (sigma=8) ----------------
__global__ void __launch_bounds__(256) pass1_l1(const float* __restrict__ xin,
                                                const float* __restrict__ yin) {
    constexpr int R = 16, ROWS = 96;
    const int b = blockIdx.y;
    const int xt = blockIdx.x & 15;
    const int yt = blockIdx.x >> 4;
    const int x0 = xt * 32, y0 = yt * 64;

    extern __shared__ float ss[];      // [3][96][32]
    __shared__ float sw[33];
    const int tid = threadIdx.x;
    if (tid < 33) sw[tid] = d_w[4][tid];

    for (int e = tid; e < ROWS * 32; e += 256) {
        int col = e & 31, row = e >> 5;
        int gy = y0 - R + row;
        #pragma unroll
        for (int f = 0; f < 3; f++) {
            float v = 0.0f;
            if (gy >= 0 && gy < IH) {
                size_t gi = (size_t)(b * 3 + f) * HW + gy * IW + x0 + col;
                v = fabsf(xin[gi] - yin[gi]);
            }
            ss[f * ROWS * 32 + e] = v;
        }
    }
    __syncthreads();

    const int lane = tid & 31, wrp = tid >> 5;
    const int base = wrp * 8;

    float acc[3][8], win[3][8];
    #pragma unroll
    for (int f = 0; f < 3; f++)
        #pragma unroll
        for (int t = 0; t < 8; t++) {
            acc[f][t] = 0.0f;
            win[f][t] = ss[f * ROWS * 32 + (base + t) * 32 + lane];
        }

    for (int kk = 0; kk <= 2 * R; kk++) {
        float wk = sw[kk];
        #pragma unroll
        for (int f = 0; f < 3; f++)
            #pragma unroll
            for (int t = 0; t < 8; t++)
                acc[f][t] = fmaf(wk, win[f][t], acc[f][t]);
        if (kk < 2 * R) {
            #pragma unroll
            for (int f = 0; f < 3; f++) {
                #pragma unroll
                for (int t = 0; t < 7; t++) win[f][t] = win[f][t + 1];
                win[f][7] = ss[f * ROWS * 32 + (base + 8 + kk) * 32 + lane];
            }
        }
    }

    #pragma unroll
    for (int f = 0; f < 3; f++) {
        size_t ob = ((size_t)f * IB + b) * HW;
        #pragma unroll
        for (int t = 0; t < 8; t++)
            d_tmpL1[ob + (size_t)(y0 + base + t) * IW + x0 + lane] = acc[f][t];
    }
}

// ---------------- L1 pass2: horizontal blur + mean over channels ----------------
__global__ void __launch_bounds__(256) pass2_l1() {
    constexpr int R = 16, COLS = 96;
    const int b = blockIdx.y;
    const int xt = blockIdx.x & 7;
    const int yt = blockIdx.x >> 3;
    const int x0 = xt * 64, y0 = yt * 32;

    extern __shared__ float ss[];      // [3][COLS][33]
    __shared__ float sw[33];
    const int tid = threadIdx.x;
    if (tid < 33) sw[tid] = d_w[4][tid];

    #pragma unroll
    for (int f = 0; f < 3; f++) {
        const float* tp = d_tmpL1 + ((size_t)f * IB + b) * HW;
        for (int e = tid; e < COLS * 32; e += 256) {
            int c = e % COLS, r = e / COLS;
            int gx = x0 - R + c;
            float v = 0.0f;
            if (gx >= 0 && gx < IW) v = tp[(size_t)(y0 + r) * IW + gx];
            ss[(f * COLS + c) * 33 + r] = v;
        }
    }
    __syncthreads();

    const int lane = tid & 31, wrp = tid >> 5;
    const int basec = wrp * 8;

    float acc[3][8], win[3][8];
    #pragma unroll
    for (int f = 0; f < 3; f++)
        #pragma unroll
        for (int t = 0; t < 8; t++) {
            acc[f][t] = 0.0f;
            win[f][t] = ss[(f * COLS + basec + t) * 33 + lane];
        }

    for (int kk = 0; kk <= 2 * R; kk++) {
        float wk = sw[kk];
        #pragma unroll
        for (int f = 0; f < 3; f++)
            #pragma unroll
            for (int t = 0; t < 8; t++)
                acc[f][t] = fmaf(wk, win[f][t], acc[f][t]);
        if (kk < 2 * R) {
            #pragma unroll
            for (int f = 0; f < 3; f++) {
                #pragma unroll
                for (int t = 0; t < 7; t++) win[f][t] = win[f][t + 1];
                win[f][7] = ss[(f * COLS + basec + 8 + kk) * 33 + lane];
            }
        }
    }

    const int gy = y0 + lane;
    #pragma unroll
    for (int t = 0; t < 8; t++) {
        float g = (acc[0][t] + acc[1][t] + acc[2][t]) * (1.0f / 3.0f);
        d_gl1[((size_t)b * IH + gy) * IW + x0 + basec + t] = g;
    }
}

// ---------------- final combine + reduce ----------------
__global__ void __launch_bounds__(256) reduceK() {
    int i = blockIdx.x * 256 + threadIdx.x;
    float prod = d_cs[0][i];
    #pragma unroll
    for (int p = 1; p < 7; p++) prod *= d_cs[p][i];
    float msl = 1.0f - d_l3[i] * prod;
    float loss = 200.0f * (0.025f * msl + 0.975f * d_gl1[i]);

    #pragma unroll
    for (int o = 16; o; o >>= 1) loss += __shfl_xor_sync(0xffffffffu, loss, o);
    __shared__ float wsum[8];
    if ((threadIdx.x & 31) == 0) wsum[threadIdx.x >> 5] = loss;
    __syncthreads();
    if (threadIdx.x == 0) {
        float s = 0.0f;
        #pragma unroll
        for (int w = 0; w < 8; w++) s += wsum[w];
        atomicAdd(&d_sum, (double)s);
    }
}

__global__ void finalK(float* out) {
    out[0] = (float)(d_sum * (1.0 / (double)NPIX));
}

// ---------------- launch ----------------
extern "C" void kernel_launch(void* const* d_in, const int* in_sizes, int n_in,
                              void* d_out, int out_size) {
    const float* x = (const float*)d_in[0];
    const float* y = (const float*)d_in[1];

    // opt-in smem sizes (>48KB variants)
    cudaFuncSetAttribute(pass1_ssim<4>,  cudaFuncAttributeMaxDynamicSharedMemorySize, 5*(64+8)*32*4);
    cudaFuncSetAttribute(pass1_ssim<6>,  cudaFuncAttributeMaxDynamicSharedMemorySize, 5*(64+12)*32*4);
    cudaFuncSetAttribute(pass1_ssim<11>, cudaFuncAttributeMaxDynamicSharedMemorySize, 5*(64+22)*32*4);
    cudaFuncSetAttribute(pass1_ssim<16>, cudaFuncAttributeMaxDynamicSharedMemorySize, 5*(64+32)*32*4);
    cudaFuncSetAttribute(pass2_ssim<4>,  cudaFuncAttributeMaxDynamicSharedMemorySize, 5*(64+8)*33*4);
    cudaFuncSetAttribute(pass2_ssim<6>,  cudaFuncAttributeMaxDynamicSharedMemorySize, 5*(64+12)*33*4);
    cudaFuncSetAttribute(pass2_ssim<11>, cudaFuncAttributeMaxDynamicSharedMemorySize, 5*(64+22)*33*4);
    cudaFuncSetAttribute(pass2_ssim<16>, cudaFuncAttributeMaxDynamicSharedMemorySize, 5*(64+32)*33*4);

    initK<<<1, 64>>>();

    // pass1 (vertical blurs); pairs grouped by sigma: [0]=s0, [1,2]=s1, [3]=s2, [4,5]=s3, [6]=s4
    pass1_ssim<4> <<<dim3(128, IB, 1), 256, 5*(64+8)*32*4 >>>(x, y, 0);
    pass1_ssim<6> <<<dim3(128, IB, 2), 256, 5*(64+12)*32*4>>>(x, y, 1);
    pass1_ssim<11><<<dim3(128, IB, 1), 256, 5*(64+22)*32*4>>>(x, y, 3);
    pass1_ssim<16><<<dim3(128, IB, 3), 256, 5*(64+32)*32*4>>>(x, y, 4);
    pass1_l1      <<<dim3(128, IB, 1), 256, 3*96*32*4      >>>(x, y);

    // pass2 (horizontal blurs + epilogue)
    pass2_ssim<4> <<<dim3(128, IB, 1), 256, 5*(64+8)*33*4 >>>(0);
    pass2_ssim<6> <<<dim3(128, IB, 2), 256, 5*(64+12)*33*4>>>(1);
    pass2_ssim<11><<<dim3(128, IB, 1), 256, 5*(64+22)*33*4>>>(3);
    pass2_ssim<16><<<dim3(128, IB, 3), 256, 5*(64+32)*33*4>>>(4);
    pass2_l1      <<<dim3(128, IB, 1), 256, 3*96*33*4     >>>();

    reduceK<<<NPIX / 256, 256>>>();
    finalK<<<1, 1>>>((float*)d_out);
}

// round 3
// speedup vs baseline: 2.7364x; 2.7364x over previous
#include <cuda_runtime.h>
#include <math.h>

#define IH 512
#define IW 512
#define HW (IH*IW)

__device__ double d_sum;

// ---------------------------------------------------------------------------
// 1D Gaussian weights, normalized as the reference does (33-tap sum),
// folded symmetric index: gw<S>(k) = weight at |offset| = k.
// constexpr FUNCTION (not static member array) so device code only ever sees
// a compile-time-folded literal -> FFMA with immediate, no ODR-use.
// ---------------------------------------------------------------------------
template<int S>
__host__ __device__ constexpr float gw(int k) {
  if (S == 0) {               // sigma 0.5
    const float w[17] = {
      0.78657070f, 0.10645080f, 2.6386700e-4f, 1.1979400e-8f, 0.f,
      0.f,0.f,0.f,0.f,0.f,0.f,0.f,0.f,0.f,0.f,0.f,0.f };
    return w[k];
  } else if (S == 1) {        // sigma 1
    const float w[17] = {
      0.39894228f, 0.24197072f, 0.05399097f, 0.00443185f, 1.3383022e-4f,
      1.4867195e-6f, 6.0758820e-9f, 0.f,0.f,0.f,0.f,0.f,0.f,0.f,0.f,0.f,0.f };
    return w[k];
  } else if (S == 2) {        // sigma 2
    const float w[17] = {
      0.19947114f, 0.17603266f, 0.12098536f, 0.06475880f, 0.02699548f,
      0.00876415f, 0.00221591f, 4.3634000e-4f, 6.6915600e-5f, 7.9918900e-6f,
      7.4336000e-7f, 5.3855000e-8f, 0.f,0.f,0.f,0.f,0.f };
    return w[k];
  } else if (S == 3) {        // sigma 4 (33-tap renormalized)
    const float w[17] = {
      0.09973910f, 0.09667042f, 0.08801943f, 0.07528699f, 0.06049481f,
      0.04566388f, 0.03238055f, 0.02157010f, 0.01349824f, 0.00793519f,
      0.00438223f, 0.00227347f, 0.00110800f, 5.0728000e-4f, 2.1818000e-4f,
      8.8149000e-5f, 3.3459000e-5f };
    return w[k];
  } else {                    // sigma 8 (33-tap renormalized)
    const float w[17] = {
      0.05189330f, 0.05148946f, 0.05029670f, 0.04836990f, 0.04579570f,
      0.04268628f, 0.03917112f, 0.03538810f, 0.03147487f, 0.02756033f,
      0.02375847f, 0.02016357f, 0.01684730f, 0.01385819f, 0.01122271f,
      0.00894759f, 0.00702300f };
    return w[k];
  }
}

// ---------------------------------------------------------------------------
// Vertical blur: scatter form. For each input row RR (relative), update all
// affected output rows T with an immediate-weight FMA.
// ---------------------------------------------------------------------------
template<int S,int NF,int R,int RR,int T,int TEND> struct VT {
  static __device__ __forceinline__ void run(float (&acc)[NF][8], const float (&v)[NF]) {
    constexpr int d = RR - T - R;
    constexpr int k = d < 0 ? -d : d;
    constexpr float W = gw<S>(k);
    #pragma unroll
    for (int f = 0; f < NF; f++)
      acc[f][T] = fmaf(W, v[f], acc[f][T]);
    VT<S,NF,R,RR,T+1,TEND>::run(acc, v);
  }
};
template<int S,int NF,int R,int RR,int TEND> struct VT<S,NF,R,RR,TEND,TEND> {
  static __device__ __forceinline__ void run(float (&)[NF][8], const float (&)[NF]) {}
};

template<int S,int R,int RR,int REND> struct VR5 {
  static __device__ __forceinline__ void run(float (&acc)[5][8],
                                             const float* sxc, const float* syc) {
    float xv = sxc[RR*64], yv = syc[RR*64];
    float v[5] = { xv, yv, xv*xv, yv*yv, xv*yv };
    constexpr int tlo = (RR - 2*R) > 0 ? (RR - 2*R) : 0;
    constexpr int thi = RR < 7 ? RR : 7;
    VT<S,5,R,RR,tlo,thi+1>::run(acc, v);
    VR5<S,R,RR+1,REND>::run(acc, sxc, syc);
  }
};
template<int S,int R,int REND> struct VR5<S,R,REND,REND> {
  static __device__ __forceinline__ void run(float (&)[5][8], const float*, const float*) {}
};

template<int S,int R,int RR,int REND> struct VR1 {
  static __device__ __forceinline__ void run(float (&acc)[1][8], const float* sdc) {
    float v[1] = { sdc[RR*64] };
    constexpr int tlo = (RR - 2*R) > 0 ? (RR - 2*R) : 0;
    constexpr int thi = RR < 7 ? RR : 7;
    VT<S,1,R,RR,tlo,thi+1>::run(acc, v);
    VR1<S,R,RR+1,REND>::run(acc, sdc);
  }
};
template<int S,int R,int REND> struct VR1<S,R,REND,REND> {
  static __device__ __forceinline__ void run(float (&)[1][8], const float*) {}
};

// ---------------------------------------------------------------------------
// Horizontal blur: scatter over columns CC; each thread produces 4 columns.
// ---------------------------------------------------------------------------
template<int S,int NF,int R,int CC,int T,int TEND> struct HT {
  static __device__ __forceinline__ void run(float (&acc)[NF][4], const float (&v)[NF]) {
    constexpr int d = CC - T - R;
    constexpr int k = d < 0 ? -d : d;
    constexpr float W = gw<S>(k);
    #pragma unroll
    for (int f = 0; f < NF; f++)
      acc[f][T] = fmaf(W, v[f], acc[f][T]);
    HT<S,NF,R,CC,T+1,TEND>::run(acc, v);
  }
};
template<int S,int NF,int R,int CC,int TEND> struct HT<S,NF,R,CC,TEND,TEND> {
  static __device__ __forceinline__ void run(float (&)[NF][4], const float (&)[NF]) {}
};

template<int S,int NF,int R,int CC,int CEND> struct HC {
  static __device__ __forceinline__ void run(float (&acc)[NF][4], const float* base) {
    float v[NF];
    #pragma unroll
    for (int f = 0; f < NF; f++) v[f] = base[(f*64 + CC)*33];
    constexpr int tlo = (CC - 2*R) > 0 ? (CC - 2*R) : 0;
    constexpr int thi = CC < 3 ? CC : 3;
    HT<S,NF,R,CC,tlo,thi+1>::run(acc, v);
    HC<S,NF,R,CC+1,CEND>::run(acc, base);
  }
};
template<int S,int NF,int R,int CEND> struct HC<S,NF,R,CEND,CEND> {
  static __device__ __forceinline__ void run(float (&)[NF][4], const float*) {}
};

// ---------------------------------------------------------------------------
// Phase drivers
// ---------------------------------------------------------------------------
template<int S,int R>
__device__ __forceinline__ void vert5(const float* sx, const float* sy, float* vb, int tid) {
  int col = tid & 63, g = tid >> 6;
  if (col < 32 + 2*R) {
    float acc[5][8];
    #pragma unroll
    for (int f = 0; f < 5; f++)
      #pragma unroll
      for (int t = 0; t < 8; t++) acc[f][t] = 0.f;
    const float* sxc = sx + (g*8 + 16 - R)*64 + (16 - R) + col;
    const float* syc = sy + (g*8 + 16 - R)*64 + (16 - R) + col;
    VR5<S,R,0,8+2*R>::run(acc, sxc, syc);
    float* vbc = vb + col*33 + g*8;
    #pragma unroll
    for (int f = 0; f < 5; f++)
      #pragma unroll
      for (int t = 0; t < 8; t++)
        vbc[f*2112 + t] = acc[f][t];
  }
}

template<int S,int R>
__device__ __forceinline__ void vert1(const float* sd, float* vb, int tid) {
  int col = tid & 63, g = tid >> 6;
  if (col < 32 + 2*R) {
    float acc[1][8];
    #pragma unroll
    for (int t = 0; t < 8; t++) acc[0][t] = 0.f;
    const float* sdc = sd + (g*8 + 16 - R)*64 + (16 - R) + col;
    VR1<S,R,0,8+2*R>::run(acc, sdc);
    float* vbc = vb + col*33 + g*8;
    #pragma unroll
    for (int t = 0; t < 8; t++) vbc[t] = acc[0][t];
  }
}

template<int S,int R>
__device__ __forceinline__ void horiz5(const float* vb, int tid, float (&acc)[5][4]) {
  int lane = tid & 31, wp = tid >> 5;
  #pragma unroll
  for (int f = 0; f < 5; f++)
    #pragma unroll
    for (int t = 0; t < 4; t++) acc[f][t] = 0.f;
  const float* base = vb + (wp*4)*33 + lane;
  HC<S,5,R,0,4+2*R>::run(acc, base);
}

template<int S,int R>
__device__ __forceinline__ void horiz1(const float* vb, int tid, float (&acc)[1][4]) {
  int lane = tid & 31, wp = tid >> 5;
  #pragma unroll
  for (int t = 0; t < 4; t++) acc[0][t] = 0.f;
  const float* base = vb + (wp*4)*33 + lane;
  HC<S,1,R,0,4+2*R>::run(acc, base);
}

// cs epilogue: accumulate cs^M into prod
template<int M>
__device__ __forceinline__ void cs_accum(const float (&a)[5][4], float (&prod)[4]) {
  #pragma unroll
  for (int t = 0; t < 4; t++) {
    float mux = a[0][t], muy = a[1][t];
    float sxy = a[4][t] - mux*muy;
    float sx2 = a[2][t] - mux*mux;
    float sy2 = a[3][t] - muy*muy;
    float cs = (2.f*sxy + 9e-4f) / (sx2 + sy2 + 9e-4f);
    float c = cs;
    if (M >= 2) c *= cs;
    if (M >= 3) c *= cs;
    prod[t] *= c;
  }
}

// cs^3 + luminance^3 (largest-sigma pair on channel 2)
__device__ __forceinline__ void cs_l_accum(const float (&a)[5][4], float (&prod)[4],
                                           float (&l3)[4]) {
  #pragma unroll
  for (int t = 0; t < 4; t++) {
    float mux = a[0][t], muy = a[1][t];
    float A = mux*muy;
    float sxy = a[4][t] - A;
    float sx2 = a[2][t] - mux*mux;
    float sy2 = a[3][t] - muy*muy;
    float cs = (2.f*sxy + 9e-4f) / (sx2 + sy2 + 9e-4f);
    prod[t] *= cs*cs*cs;
    float l = (2.f*A + 1e-4f) / (mux*mux + muy*muy + 1e-4f);
    l3[t] = l*l*l;
  }
}

__device__ __forceinline__ void load_tile(const float* __restrict__ xp,
                                          const float* __restrict__ yp,
                                          float* sx, float* sy, float* sd,
                                          int x0, int y0, int tid, bool first) {
  #pragma unroll
  for (int i = 0; i < 16; i++) {
    int e = tid + i*256;
    int row = e >> 6, col = e & 63;
    int gy = y0 - 16 + row, gx = x0 - 16 + col;
    float xv = 0.f, yv = 0.f;
    if ((unsigned)gy < 512u && (unsigned)gx < 512u) {
      int gi = (gy << 9) + gx;
      xv = __ldg(xp + gi); yv = __ldg(yp + gi);
    }
    sx[e] = xv; sy[e] = yv;
    float d = fabsf(xv - yv);
    sd[e] = first ? d : (sd[e] + d);
  }
}

// ---------------------------------------------------------------------------
// The fused kernel: one block = one 32x32 output tile of one batch image.
// ---------------------------------------------------------------------------
__global__ void __launch_bounds__(256, 2)
fusedK(const float* __restrict__ xin, const float* __restrict__ yin) {
  extern __shared__ float smem[];
  float* sx = smem;            // [64][64]
  float* sy = smem + 4096;     // [64][64]
  float* sd = smem + 8192;     // [64][64]  sum over channels of |x-y|
  float* vb = smem + 12288;    // [5][64][33] transposed vertical-blur buffer

  const int tid = threadIdx.x;
  const int bx = blockIdx.x, b = blockIdx.y;
  const int x0 = (bx & 15) << 5, y0 = (bx >> 4) << 5;

  float prod[4], l3[4], gl1[4];
  #pragma unroll
  for (int t = 0; t < 4; t++) prod[t] = 1.f;

  // ---- channel 0: sigma 0.5 (m3), sigma 1 (m2) ----
  load_tile(xin + (size_t)(b*3+0)*HW, yin + (size_t)(b*3+0)*HW, sx, sy, sd, x0, y0, tid, true);
  __syncthreads();
  vert5<0,4>(sx, sy, vb, tid);  __syncthreads();
  { float a[5][4]; horiz5<0,4>(vb, tid, a); cs_accum<3>(a, prod); } __syncthreads();
  vert5<1,6>(sx, sy, vb, tid);  __syncthreads();
  { float a[5][4]; horiz5<1,6>(vb, tid, a); cs_accum<2>(a, prod); } __syncthreads();

  // ---- channel 1: sigma 1 (m1), sigma 2 (m3), sigma 4 (m1) ----
  load_tile(xin + (size_t)(b*3+1)*HW, yin + (size_t)(b*3+1)*HW, sx, sy, sd, x0, y0, tid, false);
  __syncthreads();
  vert5<1,6>(sx, sy, vb, tid);  __syncthreads();
  { float a[5][4]; horiz5<1,6>(vb, tid, a); cs_accum<1>(a, prod); } __syncthreads();
  vert5<2,11>(sx, sy, vb, tid); __syncthreads();
  { float a[5][4]; horiz5<2,11>(vb, tid, a); cs_accum<3>(a, prod); } __syncthreads();
  vert5<3,16>(sx, sy, vb, tid); __syncthreads();
  { float a[5][4]; horiz5<3,16>(vb, tid, a); cs_accum<1>(a, prod); } __syncthreads();

  // ---- channel 2: sigma 4 (m2), sigma 8 (m3 + luminance^3) ----
  load_tile(xin + (size_t)(b*3+2)*HW, yin + (size_t)(b*3+2)*HW, sx, sy, sd, x0, y0, tid, false);
  __syncthreads();
  vert5<3,16>(sx, sy, vb, tid); __syncthreads();
  { float a[5][4]; horiz5<3,16>(vb, tid, a); cs_accum<2>(a, prod); } __syncthreads();
  vert5<4,16>(sx, sy, vb, tid); __syncthreads();
  { float a[5][4]; horiz5<4,16>(vb, tid, a); cs_l_accum(a, prod, l3); } __syncthreads();

  // ---- gaussian L1: blur( sum_c |x-y| ) with sigma 8, /3 folded into 65 ----
  vert1<4,16>(sd, vb, tid); __syncthreads();
  { float a[1][4]; horiz1<4,16>(vb, tid, a);
    #pragma unroll
    for (int t = 0; t < 4; t++) gl1[t] = a[0][t]; }

  // ---- per-pixel loss + block reduction ----
  // loss = 200*(0.025*(1 - l3*prod) + 0.975*gl1_mean) ; gl1 here = sum over ch
  //      = 5*(1 - l3*prod) + 65*gl1
  float s = 0.f;
  #pragma unroll
  for (int t = 0; t < 4; t++) {
    float msl = 1.f - l3[t]*prod[t];
    s += fmaf(65.f, gl1[t], 5.f*msl);
  }
  #pragma unroll
  for (int o = 16; o; o >>= 1) s += __shfl_xor_sync(0xffffffffu, s, o);
  __shared__ float red[8];
  if ((tid & 31) == 0) red[tid >> 5] = s;
  __syncthreads();
  if (tid == 0) {
    float r = 0.f;
    #pragma unroll
    for (int w = 0; w < 8; w++) r += red[w];
    atomicAdd(&d_sum, (double)r);
  }
}

__global__ void initK() { d_sum = 0.0; }
__global__ void finalK(float* out) { out[0] = (float)(d_sum * (1.0 / 2097152.0)); }

// ---------------------------------------------------------------------------
extern "C" void kernel_launch(void* const* d_in, const int* in_sizes, int n_in,
                              void* d_out, int out_size) {
  const float* x = (const float*)d_in[0];
  const float* y = (const float*)d_in[1];

  const int smemBytes = (12288 + 5*64*33) * 4;   // 91392 B
  cudaFuncSetAttribute(fusedK, cudaFuncAttributeMaxDynamicSharedMemorySize, smemBytes);

  initK<<<1, 1>>>();
  fusedK<<<dim3(256, 8), 256, smemBytes>>>(x, y);
  finalK<<<1, 1>>>((float*)d_out);
}

// round 4
// speedup vs baseline: 3.9734x; 1.4520x over previous
#include <cuda_runtime.h>
#include <math.h>

typedef unsigned long long ull;

#define IH 512
#define IW 512
#define HW (IH*IW)

__device__ double d_sum;

// ---------------------------------------------------------------------------
// 1D Gaussian weights (reference 33-tap normalization), folded |offset|=k.
// Tails below ~1e-7 dropped (radius: 2,5,10,16,16).
// ---------------------------------------------------------------------------
template<int S>
__host__ __device__ constexpr float gw(int k) {
  if (S == 0) {               // sigma 0.5, R=2
    const float w[17] = {
      0.78657070f, 0.10645080f, 2.6386700e-4f, 0.f,0.f,
      0.f,0.f,0.f,0.f,0.f,0.f,0.f,0.f,0.f,0.f,0.f,0.f };
    return w[k];
  } else if (S == 1) {        // sigma 1, R=5
    const float w[17] = {
      0.39894228f, 0.24197072f, 0.05399097f, 0.00443185f, 1.3383022e-4f,
      1.4867195e-6f, 0.f,0.f,0.f,0.f,0.f,0.f,0.f,0.f,0.f,0.f,0.f };
    return w[k];
  } else if (S == 2) {        // sigma 2, R=10
    const float w[17] = {
      0.19947114f, 0.17603266f, 0.12098536f, 0.06475880f, 0.02699548f,
      0.00876415f, 0.00221591f, 4.3634000e-4f, 6.6915600e-5f, 7.9918900e-6f,
      7.4336000e-7f, 0.f,0.f,0.f,0.f,0.f,0.f };
    return w[k];
  } else if (S == 3) {        // sigma 4 (33-tap renormalized), R=16
    const float w[17] = {
      0.09973910f, 0.09667042f, 0.08801943f, 0.07528699f, 0.06049481f,
      0.04566388f, 0.03238055f, 0.02157010f, 0.01349824f, 0.00793519f,
      0.00438223f, 0.00227347f, 0.00110800f, 5.0728000e-4f, 2.1818000e-4f,
      8.8149000e-5f, 3.3459000e-5f };
    return w[k];
  } else {                    // sigma 8 (33-tap renormalized), R=16
    const float w[17] = {
      0.05189330f, 0.05148946f, 0.05029670f, 0.04836990f, 0.04579570f,
      0.04268628f, 0.03917112f, 0.03538810f, 0.03147487f, 0.02756033f,
      0.02375847f, 0.02016357f, 0.01684730f, 0.01385819f, 0.01122271f,
      0.00894759f, 0.00702300f };
    return w[k];
  }
}

template<int S>
__host__ __device__ constexpr ull gw2(int k) {
  unsigned u = __builtin_bit_cast(unsigned, gw<S>(k));
  return (ull)u | ((ull)u << 32);
}

#define FMA2(acc, v, w) asm("fma.rn.f32x2 %0, %1, %2, %0;" : "+l"(acc) : "l"(v), "l"(w))
#define MUL2(d, a, b)   asm("mul.rn.f32x2 %0, %1, %2;" : "=l"(d) : "l"(a), "l"(b))
#define UNPK(lo, hi, v) asm("mov.b64 {%0,%1}, %2;" : "=f"(lo), "=f"(hi) : "l"(v))

// vb element layout: 6 floats per (col,row): [x y x2 y2 xy pad]
// column stride 198 floats (even for 8B align, ≡6 mod 32 for bank spread)
#define VB_CSTRIDE 198
#define VB_WORDS   (64*VB_CSTRIDE)   // 12672

// ---------------------------------------------------------------------------
// Vertical blur, 5-field packed. Scatter: input row RR updates outputs T.
// ---------------------------------------------------------------------------
template<int S,int R,int RR,int T,int TEND> struct VT5 {
  static __device__ __forceinline__ void run(ull (&aA)[8], ull (&aB)[8], float (&aC)[8],
                                             ull vA, ull vB, float vC) {
    constexpr int d = RR - T - R;
    constexpr int k = d < 0 ? -d : d;
    constexpr float W = gw<S>(k);
    constexpr ull W2 = gw2<S>(k);
    FMA2(aA[T], vA, W2);
    FMA2(aB[T], vB, W2);
    aC[T] = fmaf(W, vC, aC[T]);
    VT5<S,R,RR,T+1,TEND>::run(aA, aB, aC, vA, vB, vC);
  }
};
template<int S,int R,int RR,int TEND> struct VT5<S,R,RR,TEND,TEND> {
  static __device__ __forceinline__ void run(ull (&)[8], ull (&)[8], float (&)[8],
                                             ull, ull, float) {}
};

template<int S,int R,int RR,int REND> struct VR5 {
  static __device__ __forceinline__ void run(ull (&aA)[8], ull (&aB)[8], float (&aC)[8],
                                             const float* sc) {
    ull v = *(const ull*)(sc + RR*128);     // (x,y) pair, row stride 64 pairs
    float x, y; UNPK(x, y, v);
    ull vsq; MUL2(vsq, v, v);
    float xy = x * y;
    constexpr int tlo = (RR - 2*R) > 0 ? (RR - 2*R) : 0;
    constexpr int thi = RR < 7 ? RR : 7;
    VT5<S,R,RR,tlo,thi+1>::run(aA, aB, aC, v, vsq, xy);
    VR5<S,R,RR+1,REND>::run(aA, aB, aC, sc);
  }
};
template<int S,int R,int REND> struct VR5<S,R,REND,REND> {
  static __device__ __forceinline__ void run(ull (&)[8], ull (&)[8], float (&)[8],
                                             const float*) {}
};

// scalar vertical (L1 term)
template<int S,int R,int RR,int T,int TEND> struct VT1 {
  static __device__ __forceinline__ void run(float (&acc)[8], float v) {
    constexpr int d = RR - T - R;
    constexpr int k = d < 0 ? -d : d;
    constexpr float W = gw<S>(k);
    acc[T] = fmaf(W, v, acc[T]);
    VT1<S,R,RR,T+1,TEND>::run(acc, v);
  }
};
template<int S,int R,int RR,int TEND> struct VT1<S,R,RR,TEND,TEND> {
  static __device__ __forceinline__ void run(float (&)[8], float) {}
};

template<int S,int R,int RR,int REND> struct VR1 {
  static __device__ __forceinline__ void run(float (&acc)[8], const float* sdc) {
    float v = sdc[RR*64];
    constexpr int tlo = (RR - 2*R) > 0 ? (RR - 2*R) : 0;
    constexpr int thi = RR < 7 ? RR : 7;
    VT1<S,R,RR,tlo,thi+1>::run(acc, v);
    VR1<S,R,RR+1,REND>::run(acc, sdc);
  }
};
template<int S,int R,int REND> struct VR1<S,R,REND,REND> {
  static __device__ __forceinline__ void run(float (&)[8], const float*) {}
};

// ---------------------------------------------------------------------------
// Horizontal blur, packed. Scatter over columns CC; 4 outputs per thread.
// ---------------------------------------------------------------------------
template<int S,int R,int CC,int T,int TEND> struct HT5 {
  static __device__ __forceinline__ void run(ull (&aA)[4], ull (&aB)[4], float (&aC)[4],
                                             ull vA, ull vB, float vC) {
    constexpr int d = CC - T - R;
    constexpr int k = d < 0 ? -d : d;
    constexpr float W = gw<S>(k);
    constexpr ull W2 = gw2<S>(k);
    FMA2(aA[T], vA, W2);
    FMA2(aB[T], vB, W2);
    aC[T] = fmaf(W, vC, aC[T]);
    HT5<S,R,CC,T+1,TEND>::run(aA, aB, aC, vA, vB, vC);
  }
};
template<int S,int R,int CC,int TEND> struct HT5<S,R,CC,TEND,TEND> {
  static __device__ __forceinline__ void run(ull (&)[4], ull (&)[4], float (&)[4],
                                             ull, ull, float) {}
};

template<int S,int R,int CC,int CEND> struct HC5 {
  static __device__ __forceinline__ void run(ull (&aA)[4], ull (&aB)[4], float (&aC)[4],
                                             const float* base) {
    const float* p = base + CC*VB_CSTRIDE;
    ull vA = *(const ull*)(p);
    ull vB = *(const ull*)(p + 2);
    float vC = p[4];
    constexpr int tlo = (CC - 2*R) > 0 ? (CC - 2*R) : 0;
    constexpr int thi = CC < 3 ? CC : 3;
    HT5<S,R,CC,tlo,thi+1>::run(aA, aB, aC, vA, vB, vC);
    HC5<S,R,CC+1,CEND>::run(aA, aB, aC, base);
  }
};
template<int S,int R,int CEND> struct HC5<S,R,CEND,CEND> {
  static __device__ __forceinline__ void run(ull (&)[4], ull (&)[4], float (&)[4],
                                             const float*) {}
};

// scalar horizontal (L1 term)
template<int S,int R,int CC,int T,int TEND> struct HT1 {
  static __device__ __forceinline__ void run(float (&acc)[4], float v) {
    constexpr int d = CC - T - R;
    constexpr int k = d < 0 ? -d : d;
    constexpr float W = gw<S>(k);
    acc[T] = fmaf(W, v, acc[T]);
    HT1<S,R,CC,T+1,TEND>::run(acc, v);
  }
};
template<int S,int R,int CC,int TEND> struct HT1<S,R,CC,TEND,TEND> {
  static __device__ __forceinline__ void run(float (&)[4], float) {}
};

template<int S,int R,int CC,int CEND> struct HC1 {
  static __device__ __forceinline__ void run(float (&acc)[4], const float* base) {
    float v = base[CC*VB_CSTRIDE];
    constexpr int tlo = (CC - 2*R) > 0 ? (CC - 2*R) : 0;
    constexpr int thi = CC < 3 ? CC : 3;
    HT1<S,R,CC,tlo,thi+1>::run(acc, v);
    HC1<S,R,CC+1,CEND>::run(acc, base);
  }
};
template<int S,int R,int CEND> struct HC1<S,R,CEND,CEND> {
  static __device__ __forceinline__ void run(float (&)[4], const float*) {}
};

// ---------------------------------------------------------------------------
// Phase drivers
// ---------------------------------------------------------------------------
template<int S,int R>
__device__ __forceinline__ void vert5(const float* sxy, float* vb, int tid) {
  int col = tid & 63, g = tid >> 6;
  if (col < 32 + 2*R) {
    ull aA[8], aB[8]; float aC[8];
    #pragma unroll
    for (int t = 0; t < 8; t++) { aA[t] = 0ull; aB[t] = 0ull; aC[t] = 0.f; }
    const float* sc = sxy + (((g*8 + 16 - R)*64) + (16 - R) + col) * 2;
    VR5<S,R,0,8+2*R>::run(aA, aB, aC, sc);
    float* vp = vb + col*VB_CSTRIDE + g*8*6;
    #pragma unroll
    for (int t = 0; t < 8; t++) {
      *(ull*)(vp + t*6)     = aA[t];
      *(ull*)(vp + t*6 + 2) = aB[t];
      vp[t*6 + 4]           = aC[t];
    }
  }
}

__device__ __forceinline__ void vert1_s8(const float* sd, float* vb, int tid) {
  constexpr int R = 16;
  int col = tid & 63, g = tid >> 6;
  {
    float acc[8];
    #pragma unroll
    for (int t = 0; t < 8; t++) acc[t] = 0.f;
    const float* sdc = sd + (g*8 + 16 - R)*64 + (16 - R) + col;
    VR1<4,R,0,8+2*R>::run(acc, sdc);
    float* vp = vb + col*VB_CSTRIDE + g*8*6;
    #pragma unroll
    for (int t = 0; t < 8; t++) vp[t*6] = acc[t];
  }
}

template<int S,int R>
__device__ __forceinline__ void horiz5(const float* vb, int tid,
                                       ull (&aA)[4], ull (&aB)[4], float (&aC)[4]) {
  int lane = tid & 31, wp = tid >> 5;
  #pragma unroll
  for (int t = 0; t < 4; t++) { aA[t] = 0ull; aB[t] = 0ull; aC[t] = 0.f; }
  const float* base = vb + (wp*4)*VB_CSTRIDE + lane*6;
  HC5<S,R,0,4+2*R>::run(aA, aB, aC, base);
}

__device__ __forceinline__ void horiz1_s8(const float* vb, int tid, float (&acc)[4]) {
  constexpr int R = 16;
  int lane = tid & 31, wp = tid >> 5;
  #pragma unroll
  for (int t = 0; t < 4; t++) acc[t] = 0.f;
  const float* base = vb + (wp*4)*VB_CSTRIDE + lane*6;
  HC1<4,R,0,4+2*R>::run(acc, base);
}

// cs epilogue: accumulate cs^M into prod
template<int M>
__device__ __forceinline__ void cs_accum(ull (&aA)[4], ull (&aB)[4], float (&aC)[4],
                                         float (&prod)[4]) {
  #pragma unroll
  for (int t = 0; t < 4; t++) {
    float mux, muy; UNPK(mux, muy, aA[t]);
    float mxx, myy; UNPK(mxx, myy, aB[t]);
    float sxy = aC[t] - mux*muy;
    float sx2 = mxx - mux*mux;
    float sy2 = myy - muy*muy;
    float cs = (2.f*sxy + 9e-4f) / (sx2 + sy2 + 9e-4f);
    float c = cs;
    if (M >= 2) c *= cs;
    if (M >= 3) c *= cs;
    prod[t] *= c;
  }
}

__device__ __forceinline__ void cs_l_accum(ull (&aA)[4], ull (&aB)[4], float (&aC)[4],
                                           float (&prod)[4], float (&l3)[4]) {
  #pragma unroll
  for (int t = 0; t < 4; t++) {
    float mux, muy; UNPK(mux, muy, aA[t]);
    float mxx, myy; UNPK(mxx, myy, aB[t]);
    float A = mux*muy;
    float sxy = aC[t] - A;
    float sx2 = mxx - mux*mux;
    float sy2 = myy - muy*muy;
    float cs = (2.f*sxy + 9e-4f) / (sx2 + sy2 + 9e-4f);
    prod[t] *= cs*cs*cs;
    float l = (2.f*A + 1e-4f) / (mux*mux + muy*muy + 1e-4f);
    l3[t] = l*l*l;
  }
}

__device__ __forceinline__ void load_tile(const float* __restrict__ xp,
                                          const float* __restrict__ yp,
                                          float* sxy, float* sd,
                                          int x0, int y0, int tid, bool first) {
  #pragma unroll
  for (int i = 0; i < 16; i++) {
    int e = tid + i*256;
    int row = e >> 6, col = e & 63;
    int gy = y0 - 16 + row, gx = x0 - 16 + col;
    float xv = 0.f, yv = 0.f;
    if ((unsigned)gy < 512u && (unsigned)gx < 512u) {
      int gi = (gy << 9) + gx;
      xv = __ldg(xp + gi); yv = __ldg(yp + gi);
    }
    ((float2*)sxy)[e] = make_float2(xv, yv);
    float d = fabsf(xv - yv);
    sd[e] = first ? d : (sd[e] + d);
  }
}

// ---------------------------------------------------------------------------
// Fused kernel: one block = one 32x32 output tile of one batch image.
// ---------------------------------------------------------------------------
__global__ void __launch_bounds__(256, 2)
fusedK(const float* __restrict__ xin, const float* __restrict__ yin) {
  extern __shared__ float smem[];
  float* sxy = smem;              // [64][64][2]  (8192 floats)
  float* sd  = smem + 8192;       // [64][64]     (4096 floats)
  float* vb  = smem + 12288;      // [64 cols][stride 198]  (12672 floats)

  const int tid = threadIdx.x;
  const int bx = blockIdx.x, b = blockIdx.y;
  const int x0 = (bx & 15) << 5, y0 = (bx >> 4) << 5;

  float prod[4], l3[4], gl1[4];
  #pragma unroll
  for (int t = 0; t < 4; t++) prod[t] = 1.f;

  ull aA[4], aB[4]; float aC[4];

  // ---- channel 0: sigma 0.5 (m3), sigma 1 (m2) ----
  load_tile(xin + (size_t)(b*3+0)*HW, yin + (size_t)(b*3+0)*HW, sxy, sd, x0, y0, tid, true);
  __syncthreads();
  vert5<0,2>(sxy, vb, tid);  __syncthreads();
  horiz5<0,2>(vb, tid, aA, aB, aC); cs_accum<3>(aA, aB, aC, prod); __syncthreads();
  vert5<1,5>(sxy, vb, tid);  __syncthreads();
  horiz5<1,5>(vb, tid, aA, aB, aC); cs_accum<2>(aA, aB, aC, prod); __syncthreads();

  // ---- channel 1: sigma 1 (m1), sigma 2 (m3), sigma 4 (m1) ----
  load_tile(xin + (size_t)(b*3+1)*HW, yin + (size_t)(b*3+1)*HW, sxy, sd, x0, y0, tid, false);
  __syncthreads();
  vert5<1,5>(sxy, vb, tid);  __syncthreads();
  horiz5<1,5>(vb, tid, aA, aB, aC); cs_accum<1>(aA, aB, aC, prod); __syncthreads();
  vert5<2,10>(sxy, vb, tid); __syncthreads();
  horiz5<2,10>(vb, tid, aA, aB, aC); cs_accum<3>(aA, aB, aC, prod); __syncthreads();
  vert5<3,16>(sxy, vb, tid); __syncthreads();
  horiz5<3,16>(vb, tid, aA, aB, aC); cs_accum<1>(aA, aB, aC, prod); __syncthreads();

  // ---- channel 2: sigma 4 (m2), sigma 8 (m3 + luminance^3) ----
  load_tile(xin + (size_t)(b*3+2)*HW, yin + (size_t)(b*3+2)*HW, sxy, sd, x0, y0, tid, false);
  __syncthreads();
  vert5<3,16>(sxy, vb, tid); __syncthreads();
  horiz5<3,16>(vb, tid, aA, aB, aC); cs_accum<2>(aA, aB, aC, prod); __syncthreads();
  vert5<4,16>(sxy, vb, tid); __syncthreads();
  horiz5<4,16>(vb, tid, aA, aB, aC); cs_l_accum(aA, aB, aC, prod, l3); __syncthreads();

  // ---- gaussian L1: blur( sum_c |x-y| ) sigma 8; /3 folded into final 65 ----
  vert1_s8(sd, vb, tid); __syncthreads();
  { float a[4]; horiz1_s8(vb, tid, a);
    #pragma unroll
    for (int t = 0; t < 4; t++) gl1[t] = a[t]; }

  // ---- per-pixel loss + block reduction ----
  // loss = 200*(0.025*(1 - l3*prod) + 0.975*gl1/3) = 5*(1 - l3*prod) + 65*gl1
  float s = 0.f;
  #pragma unroll
  for (int t = 0; t < 4; t++) {
    float msl = 1.f - l3[t]*prod[t];
    s += fmaf(65.f, gl1[t], 5.f*msl);
  }
  #pragma unroll
  for (int o = 16; o; o >>= 1) s += __shfl_xor_sync(0xffffffffu, s, o);
  __shared__ float red[8];
  if ((tid & 31) == 0) red[tid >> 5] = s;
  __syncthreads();
  if (tid == 0) {
    float r = 0.f;
    #pragma unroll
    for (int w = 0; w < 8; w++) r += red[w];
    atomicAdd(&d_sum, (double)r);
  }
}

__global__ void finalK(float* out) { out[0] = (float)(d_sum * (1.0 / 2097152.0)); }

// ---------------------------------------------------------------------------
extern "C" void kernel_launch(void* const* d_in, const int* in_sizes, int n_in,
                              void* d_out, int out_size) {
  const float* x = (const float*)d_in[0];
  const float* y = (const float*)d_in[1];

  const int smemBytes = (12288 + VB_WORDS) * 4;   // 99,840 B
  cudaFuncSetAttribute(fusedK, cudaFuncAttributeMaxDynamicSharedMemorySize, smemBytes);

  void* sumPtr = nullptr;
  cudaGetSymbolAddress(&sumPtr, d_sum);
  cudaMemsetAsync(sumPtr, 0, sizeof(double));

  fusedK<<<dim3(256, 8), 256, smemBytes>>>(x, y);
  finalK<<<1, 1>>>((float*)d_out);
}